// round 2
// baseline (speedup 1.0000x reference)
#include <cuda_runtime.h>

#define NB 128
#define NN 784
#define NC 512
#define NK 64
#define XS_STRIDE 66

// Scratch (no allocations allowed)
__device__ float g_anchor[NK * NC];      // normalized anchors
__device__ float g_A[NB * NN];           // logsumexp_k(20 s_k) - 20
__device__ float g_w[NB * NN];           // final weights 2*sigmoid(t)/N
__device__ float g_part[8][NB * NC];     // emb partials per n-chunk

__device__ __forceinline__ void ffma2(unsigned long long& d,
                                      unsigned long long a,
                                      unsigned long long b) {
    asm("fma.rn.f32x2 %0, %1, %2, %0;" : "+l"(d) : "l"(a), "l"(b));
}

// ---------------------------------------------------------------------------
// Kernel 1: normalize anchors (64 rows of 512)
// ---------------------------------------------------------------------------
__global__ void anchor_norm_kernel(const float* __restrict__ ker) {
    int k = blockIdx.x;
    int t = threadIdx.x;  // 128
    float s = 0.f;
    float v[4];
#pragma unroll
    for (int i = 0; i < 4; i++) {
        v[i] = ker[k * NC + t + i * 128];
        s += v[i] * v[i];
    }
    __shared__ float red[4];
#pragma unroll
    for (int o = 16; o > 0; o >>= 1) s += __shfl_xor_sync(0xffffffffu, s, o);
    if ((t & 31) == 0) red[t >> 5] = s;
    __syncthreads();
    float tot = red[0] + red[1] + red[2] + red[3];
    float inv = 1.0f / (sqrtf(tot) + 1e-12f);
#pragma unroll
    for (int i = 0; i < 4; i++)
        g_anchor[k * NC + t + i * 128] = v[i] * inv;
}

// ---------------------------------------------------------------------------
// Kernel 2: fused GEMM (x . anchors^T) + per-n norm + logsumexp -> g_A
// Block: 256 threads, tile = 64 n x 64 k, loop C in chunks of 64.
// Packed fma.rn.f32x2 over (even c, odd c) lanes: no packing movs needed.
// ---------------------------------------------------------------------------
__global__ __launch_bounds__(256) void gemmA_kernel(const float* __restrict__ x) {
    __shared__ float xs[64 * XS_STRIDE];
    __shared__ float as[64 * XS_STRIDE];
    __shared__ float snrm[64];

    int b = blockIdx.y;
    int n_base = blockIdx.x * 64;
    int t = threadIdx.x;
    int tx = t & 15, ty = t >> 4;
    int lane = t & 31, wid = t >> 5;

    unsigned long long acc[4][4];
#pragma unroll
    for (int i = 0; i < 4; i++)
#pragma unroll
        for (int j = 0; j < 4; j++) acc[i][j] = 0ull;

    float prow[8];  // per-warp partial sumsq; warp w owns rows w, w+8, ..., w+56
#pragma unroll
    for (int i = 0; i < 8; i++) prow[i] = 0.f;

    const float* xrowbase = x + ((size_t)b * NN + n_base) * NC;

    for (int ch = 0; ch < 8; ch++) {
        int c0 = ch * 64;
        __syncthreads();
        // Load 64x64 x-tile and 64x64 anchor-tile (float2 granularity).
        // idx>>5 (the row) is warp-uniform each iteration: row = wid + 8*i.
#pragma unroll
        for (int i = 0; i < 8; i++) {
            int row = wid + 8 * i;
            int col = lane * 2;
            float2 v;
            int gn = n_base + row;
            if (gn < NN)
                v = *(const float2*)(xrowbase + (size_t)row * NC + c0 + col);
            else
                v = make_float2(0.f, 0.f);
            *(float2*)&xs[row * XS_STRIDE + col] = v;
            prow[i] += v.x * v.x + v.y * v.y;
            float2 a = *(const float2*)(g_anchor + row * NC + c0 + col);
            *(float2*)&as[row * XS_STRIDE + col] = a;
        }
        __syncthreads();
        // Compute: each thread owns k in {ty+16j}, n in {tx+16j}
#pragma unroll
        for (int cc = 0; cc < 64; cc += 4) {
            unsigned long long a0[4], a1[4], x0[4], x1[4];
#pragma unroll
            for (int j = 0; j < 4; j++) {
                int kr = ty + 16 * j;
                a0[j] = *(const unsigned long long*)&as[kr * XS_STRIDE + cc];
                a1[j] = *(const unsigned long long*)&as[kr * XS_STRIDE + cc + 2];
                int nr = tx + 16 * j;
                x0[j] = *(const unsigned long long*)&xs[nr * XS_STRIDE + cc];
                x1[j] = *(const unsigned long long*)&xs[nr * XS_STRIDE + cc + 2];
            }
#pragma unroll
            for (int jk = 0; jk < 4; jk++)
#pragma unroll
                for (int jn = 0; jn < 4; jn++) {
                    ffma2(acc[jk][jn], a0[jk], x0[jn]);
                    ffma2(acc[jk][jn], a1[jk], x1[jn]);
                }
        }
    }
    __syncthreads();  // all compute done; xs reusable, snrm writable

    // Per-warp reduce of sumsq partials -> snrm
#pragma unroll
    for (int i = 0; i < 8; i++) {
        float s = prow[i];
#pragma unroll
        for (int o = 16; o > 0; o >>= 1) s += __shfl_xor_sync(0xffffffffu, s, o);
        if (lane == 0) snrm[wid + 8 * i] = s;
    }

    // Scatter dot products S[k][n] into xs
#pragma unroll
    for (int jk = 0; jk < 4; jk++)
#pragma unroll
        for (int jn = 0; jn < 4; jn++) {
            union { unsigned long long u; float2 f; } cv;
            cv.u = acc[jk][jn];
            xs[(ty + 16 * jk) * XS_STRIDE + (tx + 16 * jn)] = cv.f.x + cv.f.y;
        }
    __syncthreads();

    // logsumexp over k for each valid n
    if (t < 64) {
        int gn = n_base + t;
        if (gn < NN) {
            float nrm = sqrtf(snrm[t]) + 1e-12f;
            float sc = 20.f / nrm;
            float mx = -1e30f;
#pragma unroll
            for (int k = 0; k < NK; k++) {
                float l = xs[k * XS_STRIDE + t] * sc;
                mx = fmaxf(mx, l);
            }
            float sum = 0.f;
#pragma unroll
            for (int k = 0; k < NK; k++)
                sum += expf(xs[k * XS_STRIDE + t] * sc - mx);
            g_A[b * NN + gn] = mx + logf(sum) - 20.f;
        }
    }
}

// ---------------------------------------------------------------------------
// Kernel 3: scalar Sinkhorn solve per batch + final weights
// v_{s+1} = v + eps*(log mu - log(mean_n sigmoid(v/eps + A_n))), 10 steps
// ---------------------------------------------------------------------------
__global__ void vsolve_kernel() {
    int b = blockIdx.x;
    int t = threadIdx.x;  // 256
    __shared__ float sA[NN];
    __shared__ float red[8];
    for (int i = t; i < NN; i += 256) sA[i] = g_A[b * NN + i];
    __syncthreads();

    float v = 0.f;
    const float invN = 1.f / 784.f;
    for (int s = 0; s < 10; s++) {
        float voe = v * 10.f;  // v / EPS
        float ps = 0.f;
        for (int i = t; i < NN; i += 256) {
            float tt = voe + sA[i];
            ps += 1.f / (1.f + expf(-tt));
        }
#pragma unroll
        for (int o = 16; o > 0; o >>= 1) ps += __shfl_xor_sync(0xffffffffu, ps, o);
        if ((t & 31) == 0) red[t >> 5] = ps;
        __syncthreads();
        float tot = 0.f;
#pragma unroll
        for (int w = 0; w < 8; w++) tot += red[w];  // same order on all threads
        float m = logf(tot * invN);
        v += 0.1f * (-0.6931471805599453f - m);
        __syncthreads();  // before red[] reuse next iteration
    }
    float voe = v * 10.f;
    for (int i = t; i < NN; i += 256) {
        float tt = voe + sA[i];
        g_w[b * NN + i] = (2.f * invN) / (1.f + expf(-tt));
    }
}

// ---------------------------------------------------------------------------
// Kernel 4: weighted mean partials: g_part[chunk][b*512 + c] (deterministic)
// grid = 128 b x 8 n-chunks of 98
// ---------------------------------------------------------------------------
__global__ __launch_bounds__(256) void emb_partial_kernel(const float* __restrict__ x) {
    int b = blockIdx.x >> 3;
    int chk = blockIdx.x & 7;
    int n0 = chk * 98;
    int t = threadIdx.x;  // 256, each owns float2 column pair
    __shared__ float sw[98];
    for (int i = t; i < 98; i += 256) sw[i] = g_w[b * NN + n0 + i];
    __syncthreads();

    const float2* xb = (const float2*)x + ((size_t)(b * NN + n0)) * 256 + t;
    float ax = 0.f, ay = 0.f;
#pragma unroll 7
    for (int i = 0; i < 98; i++) {
        float w = sw[i];
        float2 v = xb[(size_t)i * 256];
        ax += w * v.x;
        ay += w * v.y;
    }
    *(float2*)&g_part[chk][b * NC + t * 2] = make_float2(ax, ay);
}

// ---------------------------------------------------------------------------
// Kernel 5: deterministic reduction of the 8 partials -> output
// ---------------------------------------------------------------------------
__global__ void emb_reduce_kernel(float* __restrict__ out) {
    int i = blockIdx.x * 256 + threadIdx.x;  // 65536 total
    float s = 0.f;
#pragma unroll
    for (int j = 0; j < 8; j++) s += g_part[j][i];
    out[i] = s;
}

// ---------------------------------------------------------------------------
extern "C" void kernel_launch(void* const* d_in, const int* in_sizes, int n_in,
                              void* d_out, int out_size) {
    const float* x = (const float*)d_in[0];     // bow_feats [128,28,28,512]
    const float* ker = (const float*)d_in[1];   // kernel [64,512]
    float* out = (float*)d_out;                 // [128,512]

    anchor_norm_kernel<<<64, 128>>>(ker);
    dim3 g(13, 128);  // 13 n-tiles of 64 (784), 128 batches
    gemmA_kernel<<<g, 256>>>(x);
    vsolve_kernel<<<NB, 256>>>();
    emb_partial_kernel<<<NB * 8, 256>>>(x);
    emb_reduce_kernel<<<(NB * NC) / 256, 256>>>(out);
}

// round 8
// speedup vs baseline: 1.7684x; 1.7684x over previous
#include <cuda_runtime.h>
#include <cuda_bf16.h>
#include <cstdint>

#define NB 128
#define NN 784
#define NC 512
#define NK 64
#define XSTR 68   // smem row stride (floats) for 64-col tiles: conflict-free frags

// Scratch (no allocations allowed)
__device__ float g_anorm[NK * NC];   // normalized anchors, tf32-rounded fp32 bits
__device__ float g_A[NB * NN];       // log(sum_k exp(20 s_k)) - 20, flat (b*784+n)
__device__ float g_w[NB * NN];       // final weights 2*sigmoid(t)/N
__device__ float g_part[8][NB * NC]; // emb partials per n-chunk

// ------------------------- helpers -----------------------------------------
__device__ __forceinline__ uint32_t f2tf32(float f) {
    uint32_t r;
    asm("cvt.rna.tf32.f32 %0, %1;" : "=r"(r) : "f"(f));
    return r;
}

__device__ __forceinline__ void mma_tf32(float* c, const uint32_t* a, const uint32_t* b) {
    asm("mma.sync.aligned.m16n8k8.row.col.f32.tf32.tf32.f32 "
        "{%0,%1,%2,%3}, {%4,%5,%6,%7}, {%8,%9}, {%0,%1,%2,%3};"
        : "+f"(c[0]), "+f"(c[1]), "+f"(c[2]), "+f"(c[3])
        : "r"(a[0]), "r"(a[1]), "r"(a[2]), "r"(a[3]), "r"(b[0]), "r"(b[1]));
}

// e^x on the FMA/ALU pipes (no MUFU). Valid for |x| <= ~80.
__device__ __forceinline__ float fexp(float x) {
    float y = fmaf(x, 1.4426950408889634f, 12582912.0f);  // round(x*log2e) in low bits
    float r = y - 12582912.0f;
    float f = fmaf(x, 1.4426950408889634f, -r);           // frac in [-0.5, 0.5]
    float p = 1.3387103e-3f;
    p = fmaf(p, f, 9.6183509e-3f);
    p = fmaf(p, f, 5.5504046e-2f);
    p = fmaf(p, f, 2.4022650e-1f);
    p = fmaf(p, f, 6.9314718e-1f);
    p = fmaf(p, f, 1.0f);
    // exponent add: (bits(y) << 23) == i << 23 exactly (magic-constant trick)
    return __int_as_float(__float_as_int(p) + (__float_as_int(y) << 23));
}

// ---------------------------------------------------------------------------
// Kernel 1: normalize anchors (64 rows of 512), store tf32-rounded
// ---------------------------------------------------------------------------
__global__ void anchor_norm_kernel(const float* __restrict__ ker) {
    int k = blockIdx.x;
    int t = threadIdx.x;  // 128
    float s = 0.f;
    float v[4];
#pragma unroll
    for (int i = 0; i < 4; i++) {
        v[i] = ker[k * NC + t + i * 128];
        s += v[i] * v[i];
    }
    __shared__ float red[4];
#pragma unroll
    for (int o = 16; o > 0; o >>= 1) s += __shfl_xor_sync(0xffffffffu, s, o);
    if ((t & 31) == 0) red[t >> 5] = s;
    __syncthreads();
    float tot = red[0] + red[1] + red[2] + red[3];
    float inv = 1.0f / (sqrtf(tot) + 1e-12f);
#pragma unroll
    for (int i = 0; i < 4; i++)
        g_anorm[k * NC + t + i * 128] = __uint_as_float(f2tf32(v[i] * inv));
}

// ---------------------------------------------------------------------------
// Kernel 2: tf32 mma.sync GEMM (X[128x512] . anchors^T[512x64]) + norms
//           + no-max logsumexp epilogue -> g_A.   Grid: 784 blocks x 256 thr.
// Warp w: wm=w>>2 (2 m-tiles of 16 anchors), wn=w&3 (4 n-tiles of 8 X rows).
// ---------------------------------------------------------------------------
__global__ __launch_bounds__(256) void gemmA_mma(const float* __restrict__ x) {
    extern __shared__ float sm[];
    float* Xs = sm;                       // 128 x XSTR
    float* As = sm + 128 * XSTR;          // 64 x XSTR
    float* snrm = sm + 128 * XSTR + 64 * XSTR;  // 128

    int t = threadIdx.x;
    int lane = t & 31, w = t >> 5;
    int wm = w >> 2, wn = w & 3;
    int lr = lane >> 2, lc = lane & 3;

    float acc[2][4][4];
#pragma unroll
    for (int i = 0; i < 2; i++)
#pragma unroll
        for (int j = 0; j < 4; j++)
#pragma unroll
            for (int q = 0; q < 4; q++) acc[i][j][q] = 0.f;

    // loader mapping: 16 threads per row-slot, 8 row-slots of 16 rows
    int lrow = t >> 4, lcol = t & 15;
    float prow[8];
#pragma unroll
    for (int i = 0; i < 8; i++) prow[i] = 0.f;

    const float* xb = x + (size_t)blockIdx.x * 128 * NC;

    for (int ch = 0; ch < 8; ch++) {
        __syncthreads();  // previous chunk's frag reads done before overwrite
        const float* xc = xb + ch * 64;
#pragma unroll
        for (int i = 0; i < 8; i++) {
            int row = lrow + 16 * i;
            float4 v = *(const float4*)(xc + (size_t)row * NC + lcol * 4);
            prow[i] += v.x * v.x + v.y * v.y + v.z * v.z + v.w * v.w;
            float4 tv;
            tv.x = __uint_as_float(f2tf32(v.x));
            tv.y = __uint_as_float(f2tf32(v.y));
            tv.z = __uint_as_float(f2tf32(v.z));
            tv.w = __uint_as_float(f2tf32(v.w));
            *(float4*)&Xs[row * XSTR + lcol * 4] = tv;
        }
#pragma unroll
        for (int i = 0; i < 4; i++) {
            int idx = t + 256 * i;        // 1024 float4 = 64 rows x 16
            int ar = idx >> 4, ac = idx & 15;
            float4 a = *(const float4*)(g_anorm + (size_t)ar * NC + ch * 64 + ac * 4);
            *(float4*)&As[ar * XSTR + ac * 4] = a;
        }
        __syncthreads();

#pragma unroll
        for (int ks = 0; ks < 8; ks++) {
            int c0 = ks * 8;
            uint32_t af[2][4], bf[4][2];
#pragma unroll
            for (int mt = 0; mt < 2; mt++) {
                int ar = wm * 32 + mt * 16 + lr;
                int ac = c0 + lc;
                af[mt][0] = __float_as_uint(As[ar * XSTR + ac]);
                af[mt][1] = __float_as_uint(As[(ar + 8) * XSTR + ac]);
                af[mt][2] = __float_as_uint(As[ar * XSTR + ac + 4]);
                af[mt][3] = __float_as_uint(As[(ar + 8) * XSTR + ac + 4]);
            }
#pragma unroll
            for (int nt = 0; nt < 4; nt++) {
                int br = wn * 32 + nt * 8 + lr;
                int bc = c0 + lc;
                bf[nt][0] = __float_as_uint(Xs[br * XSTR + bc]);
                bf[nt][1] = __float_as_uint(Xs[br * XSTR + bc + 4]);
            }
#pragma unroll
            for (int mt = 0; mt < 2; mt++)
#pragma unroll
                for (int nt = 0; nt < 4; nt++)
                    mma_tf32(acc[mt][nt], af[mt], bf[nt]);
        }
    }

    // per-row sumsq: reduce across the 16 loader threads of each row (half-warp)
#pragma unroll
    for (int i = 0; i < 8; i++) {
        float s = prow[i];
#pragma unroll
        for (int o = 8; o > 0; o >>= 1) s += __shfl_xor_sync(0xffffffffu, s, o);
        if ((lane & 15) == 0) snrm[lrow + 16 * i] = s;
    }
    __syncthreads();  // frag reads done; snrm ready; Xs reusable as S^T

    // scatter D into S^T[n][m], stride 65 (reuses Xs area)
    float* St = Xs;
#pragma unroll
    for (int mt = 0; mt < 2; mt++)
#pragma unroll
        for (int nt = 0; nt < 4; nt++) {
            int m = wm * 32 + mt * 16 + lr;
            int n = wn * 32 + nt * 8 + 2 * lc;
            St[n * 65 + m] = acc[mt][nt][0];
            St[(n + 1) * 65 + m] = acc[mt][nt][1];
            St[n * 65 + m + 8] = acc[mt][nt][2];
            St[(n + 1) * 65 + m + 8] = acc[mt][nt][3];
        }
    __syncthreads();

    // logsumexp (no max-sub; logits in [-20,20]): 2 threads per row
    {
        int row = t >> 1, h = t & 1;
        float sc = 20.f / (sqrtf(snrm[row]) + 1e-12f);
        const float* Sr = &St[row * 65 + h * 32];
        float sum = 0.f;
#pragma unroll
        for (int k = 0; k < 32; k++) sum += fexp(Sr[k] * sc);
        sum += __shfl_xor_sync(0xffffffffu, sum, 1);
        if (h == 0)
            g_A[(size_t)blockIdx.x * 128 + row] = __logf(sum) - 20.f;
    }
}

// ---------------------------------------------------------------------------
// Kernel 3: scalar Sinkhorn solve per batch + final weights
// ---------------------------------------------------------------------------
__global__ void vsolve_kernel() {
    int b = blockIdx.x;
    int t = threadIdx.x;  // 256
    __shared__ float sA[NN];
    __shared__ float red[8];
    for (int i = t; i < NN; i += 256) sA[i] = g_A[b * NN + i];
    __syncthreads();

    float v = 0.f;
    const float invN = 1.f / 784.f;
    for (int s = 0; s < 10; s++) {
        float voe = v * 10.f;  // v / EPS
        float ps = 0.f;
        for (int i = t; i < NN; i += 256) {
            float tt = voe + sA[i];
            ps += 1.f / (1.f + fexp(-tt));
        }
#pragma unroll
        for (int o = 16; o > 0; o >>= 1) ps += __shfl_xor_sync(0xffffffffu, ps, o);
        if ((t & 31) == 0) red[t >> 5] = ps;
        __syncthreads();
        float tot = 0.f;
#pragma unroll
        for (int w = 0; w < 8; w++) tot += red[w];
        float m = logf(tot * invN);
        v += 0.1f * (-0.6931471805599453f - m);
        __syncthreads();
    }
    float voe = v * 10.f;
    for (int i = t; i < NN; i += 256) {
        float tt = voe + sA[i];
        g_w[b * NN + i] = (2.f * invN) / (1.f + fexp(-tt));
    }
}

// ---------------------------------------------------------------------------
// Kernel 4: weighted mean partials (float4, reversed block order for L2 reuse)
// ---------------------------------------------------------------------------
__global__ __launch_bounds__(128) void emb_partial_kernel(const float* __restrict__ x) {
    int rb = (NB * 8 - 1) - (int)blockIdx.x;
    int b = rb >> 3;
    int chk = rb & 7;
    int n0 = chk * 98;
    int t = threadIdx.x;  // 128 threads, one float4 column group each
    __shared__ float sw_[98];
    for (int i = t; i < 98; i += 128) sw_[i] = g_w[b * NN + n0 + i];
    __syncthreads();

    const float4* xb = (const float4*)(x + ((size_t)(b * NN + n0)) * NC) + t;
    float ax = 0.f, ay = 0.f, az = 0.f, aw = 0.f;
#pragma unroll 7
    for (int i = 0; i < 98; i++) {
        float w = sw_[i];
        float4 v = xb[(size_t)i * 128];
        ax += w * v.x; ay += w * v.y; az += w * v.z; aw += w * v.w;
    }
    *(float4*)&g_part[chk][b * NC + t * 4] = make_float4(ax, ay, az, aw);
}

// ---------------------------------------------------------------------------
// Kernel 5: deterministic reduction of the 8 partials -> output
// ---------------------------------------------------------------------------
__global__ void emb_reduce_kernel(float* __restrict__ out) {
    int i = blockIdx.x * 256 + threadIdx.x;  // 65536 total
    float s = 0.f;
#pragma unroll
    for (int j = 0; j < 8; j++) s += g_part[j][i];
    out[i] = s;
}

// ---------------------------------------------------------------------------
extern "C" void kernel_launch(void* const* d_in, const int* in_sizes, int n_in,
                              void* d_out, int out_size) {
    const float* x = (const float*)d_in[0];    // bow_feats [128,28,28,512]
    const float* ker = (const float*)d_in[1];  // kernel [64,512]
    float* out = (float*)d_out;                // [128,512]

    const int smem = (128 * XSTR + 64 * XSTR + 128) * 4;
    cudaFuncSetAttribute(gemmA_mma, cudaFuncAttributeMaxDynamicSharedMemorySize, smem);

    anchor_norm_kernel<<<64, 128>>>(ker);
    gemmA_mma<<<784, 256, smem>>>(x);
    vsolve_kernel<<<NB, 256>>>();
    emb_partial_kernel<<<NB * 8, 128>>>(x);
    emb_reduce_kernel<<<(NB * NC) / 256, 256>>>(out);
}

// round 9
// speedup vs baseline: 2.1184x; 1.1980x over previous
#include <cuda_runtime.h>
#include <cuda_bf16.h>
#include <cstdint>

#define NB 128
#define NN 784
#define NC 512
#define NK 64
#define XSTR 68   // smem row stride (floats): conflict-free frag reads, 16B-aligned rows

// smem float offsets
#define XOFF0 0
#define XOFF1 (128 * XSTR)
#define AOFF0 (2 * 128 * XSTR)
#define AOFF1 (AOFF0 + 64 * XSTR)
#define NRMOFF (AOFF1 + 64 * XSTR)
#define SMEM_FLOATS (NRMOFF + 128)

// Scratch (no allocations allowed)
__device__ float g_anorm[NK * NC];   // normalized anchors, tf32(rna)-rounded
__device__ float g_A[NB * NN];       // log(sum_k exp(20 s_k)) - 20
__device__ float g_w[NB * NN];       // final weights 2*sigmoid(t)/N
__device__ float g_part[8][NB * NC]; // emb partials per n-chunk

// ------------------------- helpers -----------------------------------------
__device__ __forceinline__ uint32_t f2tf32(float f) {
    uint32_t r;
    asm("cvt.rna.tf32.f32 %0, %1;" : "=r"(r) : "f"(f));
    return r;
}

__device__ __forceinline__ uint32_t smem_u32(const void* p) {
    uint32_t a;
    asm("{ .reg .u64 t; cvta.to.shared.u64 t, %1; cvt.u32.u64 %0, t; }"
        : "=r"(a) : "l"(p));
    return a;
}

__device__ __forceinline__ void cp16(uint32_t dst, const void* src) {
    asm volatile("cp.async.cg.shared.global [%0], [%1], 16;"
                 :: "r"(dst), "l"(src));
}

__device__ __forceinline__ void mma_tf32(float* c, const uint32_t* a, const uint32_t* b) {
    asm("mma.sync.aligned.m16n8k8.row.col.f32.tf32.tf32.f32 "
        "{%0,%1,%2,%3}, {%4,%5,%6,%7}, {%8,%9}, {%0,%1,%2,%3};"
        : "+f"(c[0]), "+f"(c[1]), "+f"(c[2]), "+f"(c[3])
        : "r"(a[0]), "r"(a[1]), "r"(a[2]), "r"(a[3]), "r"(b[0]), "r"(b[1]));
}

// e^x on the FMA/ALU pipes (no MUFU). Valid for |x| <= ~80.
__device__ __forceinline__ float fexp(float x) {
    float y = fmaf(x, 1.4426950408889634f, 12582912.0f);
    float r = y - 12582912.0f;
    float f = fmaf(x, 1.4426950408889634f, -r);
    float p = 1.3387103e-3f;
    p = fmaf(p, f, 9.6183509e-3f);
    p = fmaf(p, f, 5.5504046e-2f);
    p = fmaf(p, f, 2.4022650e-1f);
    p = fmaf(p, f, 6.9314718e-1f);
    p = fmaf(p, f, 1.0f);
    return __int_as_float(__float_as_int(p) + (__float_as_int(y) << 23));
}

// ---------------------------------------------------------------------------
// Kernel 1: normalize anchors (64 rows of 512), store tf32-rounded
// ---------------------------------------------------------------------------
__global__ void anchor_norm_kernel(const float* __restrict__ ker) {
    int k = blockIdx.x;
    int t = threadIdx.x;  // 128
    float s = 0.f;
    float v[4];
#pragma unroll
    for (int i = 0; i < 4; i++) {
        v[i] = ker[k * NC + t + i * 128];
        s += v[i] * v[i];
    }
    __shared__ float red[4];
#pragma unroll
    for (int o = 16; o > 0; o >>= 1) s += __shfl_xor_sync(0xffffffffu, s, o);
    if ((t & 31) == 0) red[t >> 5] = s;
    __syncthreads();
    float tot = red[0] + red[1] + red[2] + red[3];
    float inv = 1.0f / (sqrtf(tot) + 1e-12f);
#pragma unroll
    for (int i = 0; i < 4; i++)
        g_anorm[k * NC + t + i * 128] = __uint_as_float(f2tf32(v[i] * inv));
}

// ---------------------------------------------------------------------------
// Kernel 2: cp.async double-buffered tf32 mma.sync GEMM + masked-sumsq norms
//           + no-max logsumexp epilogue.  Grid: 784 x 256 threads.
// X fed RAW fp32 to the tensor core (hw truncates to tf32); the norm is
// computed on identically-truncated values so the scale bias cancels in
// s = x.a/||x||.
// ---------------------------------------------------------------------------
__global__ __launch_bounds__(256) void gemmA_mma(const float* __restrict__ x) {
    extern __shared__ float sm[];
    uint32_t sbase = smem_u32(sm);

    int t = threadIdx.x;
    int lane = t & 31, w = t >> 5;
    int wm = w >> 2, wn = w & 3;
    int lr = lane >> 2, lc = lane & 3;

    float acc[2][4][4];
#pragma unroll
    for (int i = 0; i < 2; i++)
#pragma unroll
        for (int j = 0; j < 4; j++)
#pragma unroll
            for (int q = 0; q < 4; q++) acc[i][j][q] = 0.f;

    const float* xb = x + (size_t)blockIdx.x * 128 * NC;
    float prow = 0.f;  // sumsq: this lane owns row w*16 + (lane>>1), half lane&1
    int srow = w * 16 + (lane >> 1);
    int shalf = (lane & 1) * 32;

    // ---- stage loader: 8 X float4 + 4 A float4 per thread via cp.async ----
    int ldrow = t >> 4, ldc4 = (t & 15) * 4;
#define LOAD_STAGE(S, CH)                                                      \
    do {                                                                       \
        const float* xc = xb + (CH) * 64;                                      \
        uint32_t xd = sbase + (((S) ? XOFF1 : XOFF0) + ldrow * XSTR + ldc4) * 4; \
        _Pragma("unroll")                                                      \
        for (int i = 0; i < 8; i++)                                            \
            cp16(xd + i * 16 * XSTR * 4,                                       \
                 xc + (size_t)(ldrow + 16 * i) * NC + ldc4);                   \
        const float* ac = g_anorm + (CH) * 64;                                 \
        uint32_t ad = sbase + (((S) ? AOFF1 : AOFF0) + ldrow * XSTR + ldc4) * 4; \
        _Pragma("unroll")                                                      \
        for (int i = 0; i < 4; i++)                                            \
            cp16(ad + i * 16 * XSTR * 4,                                       \
                 ac + (size_t)(ldrow + 16 * i) * NC + ldc4);                   \
        asm volatile("cp.async.commit_group;");                                \
    } while (0)

    LOAD_STAGE(0, 0);

    for (int ch = 0; ch < 8; ch++) {
        if (ch < 7) {
            LOAD_STAGE((ch + 1) & 1, ch + 1);
            asm volatile("cp.async.wait_group 1;");
        } else {
            asm volatile("cp.async.wait_group 0;");
        }
        __syncthreads();

        const float* Xs = sm + ((ch & 1) ? XOFF1 : XOFF0);
        const float* As = sm + ((ch & 1) ? AOFF1 : AOFF0);

        // ---- sumsq on tf32-truncated values (8 LDS.128 per lane) ----
        const uint4* rp = (const uint4*)(Xs + srow * XSTR + shalf);
#pragma unroll
        for (int i = 0; i < 8; i++) {
            uint4 v = rp[i];
            float a0 = __uint_as_float(v.x & 0xFFFFE000u);
            float a1 = __uint_as_float(v.y & 0xFFFFE000u);
            float a2 = __uint_as_float(v.z & 0xFFFFE000u);
            float a3 = __uint_as_float(v.w & 0xFFFFE000u);
            prow = fmaf(a0, a0, prow);
            prow = fmaf(a1, a1, prow);
            prow = fmaf(a2, a2, prow);
            prow = fmaf(a3, a3, prow);
        }

        // ---- MMA: 8 k-steps of k=8 ----
#pragma unroll
        for (int ks = 0; ks < 8; ks++) {
            int c0 = ks * 8;
            uint32_t af[2][4], bf[4][2];
#pragma unroll
            for (int mt = 0; mt < 2; mt++) {
                int ar = wm * 32 + mt * 16 + lr;
                int ac = c0 + lc;
                af[mt][0] = __float_as_uint(As[ar * XSTR + ac]);
                af[mt][1] = __float_as_uint(As[(ar + 8) * XSTR + ac]);
                af[mt][2] = __float_as_uint(As[ar * XSTR + ac + 4]);
                af[mt][3] = __float_as_uint(As[(ar + 8) * XSTR + ac + 4]);
            }
#pragma unroll
            for (int nt = 0; nt < 4; nt++) {
                int br = wn * 32 + nt * 8 + lr;
                int bc = c0 + lc;
                bf[nt][0] = __float_as_uint(Xs[br * XSTR + bc]);
                bf[nt][1] = __float_as_uint(Xs[br * XSTR + bc + 4]);
            }
#pragma unroll
            for (int mt = 0; mt < 2; mt++)
#pragma unroll
                for (int nt = 0; nt < 4; nt++)
                    mma_tf32(acc[mt][nt], af[mt], bf[nt]);
        }
        __syncthreads();  // reads done -> next stage may overwrite this buffer
    }

    // ---- combine half-row sumsq, publish snrm ----
    float* snrm = sm + NRMOFF;
    prow += __shfl_xor_sync(0xffffffffu, prow, 1);
    if ((lane & 1) == 0) snrm[srow] = prow;

    // ---- scatter D into S^T[n][m] (reuses stage-0 X region) ----
    float* St = sm + XOFF0;
    __syncthreads();
#pragma unroll
    for (int mt = 0; mt < 2; mt++)
#pragma unroll
        for (int nt = 0; nt < 4; nt++) {
            int m = wm * 32 + mt * 16 + lr;
            int n = wn * 32 + nt * 8 + 2 * lc;
            St[n * 65 + m] = acc[mt][nt][0];
            St[(n + 1) * 65 + m] = acc[mt][nt][1];
            St[n * 65 + m + 8] = acc[mt][nt][2];
            St[(n + 1) * 65 + m + 8] = acc[mt][nt][3];
        }
    __syncthreads();

    // ---- logsumexp (no max-sub; logits in [-20,20]): 2 threads per row ----
    {
        int row = t >> 1, h = t & 1;
        float sc = 20.f / (sqrtf(snrm[row]) + 1e-12f);
        const float* Sr = &St[row * 65 + h * 32];
        float sum = 0.f;
#pragma unroll
        for (int k = 0; k < 32; k++) sum += fexp(Sr[k] * sc);
        sum += __shfl_xor_sync(0xffffffffu, sum, 1);
        if (h == 0)
            g_A[(size_t)blockIdx.x * 128 + row] = __logf(sum) - 20.f;
    }
}

// ---------------------------------------------------------------------------
// Kernel 3: scalar Sinkhorn solve per batch + final weights
// ---------------------------------------------------------------------------
__global__ void vsolve_kernel() {
    int b = blockIdx.x;
    int t = threadIdx.x;  // 256
    __shared__ float sA[NN];
    __shared__ float red[8];
    for (int i = t; i < NN; i += 256) sA[i] = g_A[b * NN + i];
    __syncthreads();

    float v = 0.f;
    const float invN = 1.f / 784.f;
    for (int s = 0; s < 10; s++) {
        float voe = v * 10.f;  // v / EPS
        float ps = 0.f;
        for (int i = t; i < NN; i += 256) {
            float tt = voe + sA[i];
            ps += 1.f / (1.f + fexp(-tt));
        }
#pragma unroll
        for (int o = 16; o > 0; o >>= 1) ps += __shfl_xor_sync(0xffffffffu, ps, o);
        if ((t & 31) == 0) red[t >> 5] = ps;
        __syncthreads();
        float tot = 0.f;
#pragma unroll
        for (int w = 0; w < 8; w++) tot += red[w];
        float m = logf(tot * invN);
        v += 0.1f * (-0.6931471805599453f - m);
        __syncthreads();
    }
    float voe = v * 10.f;
    for (int i = t; i < NN; i += 256) {
        float tt = voe + sA[i];
        g_w[b * NN + i] = (2.f * invN) / (1.f + fexp(-tt));
    }
}

// ---------------------------------------------------------------------------
// Kernel 4: weighted mean partials (float4, reversed block order, deep unroll)
// ---------------------------------------------------------------------------
__global__ __launch_bounds__(128) void emb_partial_kernel(const float* __restrict__ x) {
    int rb = (NB * 8 - 1) - (int)blockIdx.x;
    int b = rb >> 3;
    int chk = rb & 7;
    int n0 = chk * 98;
    int t = threadIdx.x;  // 128 threads, one float4 column group each
    __shared__ float sw_[98];
    for (int i = t; i < 98; i += 128) sw_[i] = g_w[b * NN + n0 + i];
    __syncthreads();

    const float4* xb = (const float4*)(x + ((size_t)(b * NN + n0)) * NC) + t;
    float ax = 0.f, ay = 0.f, az = 0.f, aw = 0.f;
#pragma unroll 14
    for (int i = 0; i < 98; i++) {
        float w = sw_[i];
        float4 v = xb[(size_t)i * 128];
        ax += w * v.x; ay += w * v.y; az += w * v.z; aw += w * v.w;
    }
    *(float4*)&g_part[chk][b * NC + t * 4] = make_float4(ax, ay, az, aw);
}

// ---------------------------------------------------------------------------
// Kernel 5: deterministic reduction of the 8 partials -> output
// ---------------------------------------------------------------------------
__global__ void emb_reduce_kernel(float* __restrict__ out) {
    int i = blockIdx.x * 256 + threadIdx.x;  // 65536 total
    float s = 0.f;
#pragma unroll
    for (int j = 0; j < 8; j++) s += g_part[j][i];
    out[i] = s;
}

// ---------------------------------------------------------------------------
extern "C" void kernel_launch(void* const* d_in, const int* in_sizes, int n_in,
                              void* d_out, int out_size) {
    const float* x = (const float*)d_in[0];    // bow_feats [128,28,28,512]
    const float* ker = (const float*)d_in[1];  // kernel [64,512]
    float* out = (float*)d_out;                // [128,512]

    const int smem = SMEM_FLOATS * 4;  // 104960 B
    cudaFuncSetAttribute(gemmA_mma, cudaFuncAttributeMaxDynamicSharedMemorySize, smem);

    anchor_norm_kernel<<<64, 128>>>(ker);
    gemmA_mma<<<784, 256, smem>>>(x);
    vsolve_kernel<<<NB, 256>>>();
    emb_partial_kernel<<<NB * 8, 128>>>(x);
    emb_reduce_kernel<<<(NB * NC) / 256, 256>>>(out);
}